// round 1
// baseline (speedup 1.0000x reference)
#include <cuda_runtime.h>
#include <math.h>

#define SCALE 0.125f
#define EPSA 1e-8f
#define LN_EPS 1e-5f

// scratch (device globals; no allocation allowed)
__device__ float g_slots[64*7*64];
__device__ float g_ug[64*7*64];
__device__ float g_ub[64*7];
__device__ float g_P[256*7*64];   // per (b,chunk) partial numerators
__device__ float g_D[256*7];      // per (b,chunk) partial denominators

// ---------------------------------------------------------------------------
// Kernel 1: per-batch slot-side prep.
// s = LN(slots; g_sl, be_sl); q = s@Wq^T + bq; u = q@Wk
// g_ug = SCALE * u * g_in ; g_ub = SCALE * (u . be_in + q . bk)
// ---------------------------------------------------------------------------
__global__ void slot_prep(const float* __restrict__ noise, const float* __restrict__ mu,
                          const float* __restrict__ sigma,
                          const float* __restrict__ Wq, const float* __restrict__ bq,
                          const float* __restrict__ Wk, const float* __restrict__ bk,
                          const float* __restrict__ g_sl, const float* __restrict__ be_sl,
                          const float* __restrict__ g_in, const float* __restrict__ be_in,
                          int first)
{
    __shared__ float sh_s[7][64];
    __shared__ float sh_q[7][64];
    int b = blockIdx.x;
    int tid = threadIdx.x, w = tid >> 5, lane = tid & 31;

    if (first) {
        for (int idx = tid; idx < 7*64; idx += blockDim.x) {
            int c = idx & 63;
            g_slots[b*448 + idx] = mu[c] + sigma[c] * noise[b*448 + idx];
        }
    }
    __syncthreads();

    if (w < 7) {
        float v0 = g_slots[b*448 + w*64 + lane];
        float v1 = g_slots[b*448 + w*64 + 32 + lane];
        float s = v0 + v1, ss = v0*v0 + v1*v1;
        #pragma unroll
        for (int o = 16; o; o >>= 1) {
            s  += __shfl_xor_sync(0xffffffffu, s,  o);
            ss += __shfl_xor_sync(0xffffffffu, ss, o);
        }
        float m   = s * (1.0f/64.0f);
        float inv = rsqrtf(ss * (1.0f/64.0f) - m*m + LN_EPS);
        sh_s[w][lane]      = (v0 - m)*inv*g_sl[lane]      + be_sl[lane];
        sh_s[w][lane + 32] = (v1 - m)*inv*g_sl[lane + 32] + be_sl[lane + 32];
    }
    __syncthreads();

    if (w < 7) {
        #pragma unroll
        for (int h = 0; h < 2; h++) {
            int c = lane + 32*h;
            float acc = bq[c];
            for (int d = 0; d < 64; d++) acc += sh_s[w][d] * Wq[c*64 + d];
            sh_q[w][c] = acc;
        }
    }
    __syncthreads();

    if (w < 7) {
        float u0 = 0.f, u1 = 0.f;
        for (int c = 0; c < 64; c++) {
            float qv = sh_q[w][c];
            u0 += qv * Wk[c*64 + lane];
            u1 += qv * Wk[c*64 + lane + 32];
        }
        g_ug[b*448 + w*64 + lane]      = u0 * g_in[lane]      * SCALE;
        g_ug[b*448 + w*64 + lane + 32] = u1 * g_in[lane + 32] * SCALE;
        float part = u0*be_in[lane] + u1*be_in[lane+32]
                   + sh_q[w][lane]*bk[lane] + sh_q[w][lane+32]*bk[lane+32];
        #pragma unroll
        for (int o = 16; o; o >>= 1) part += __shfl_xor_sync(0xffffffffu, part, o);
        if (lane == 0) g_ub[b*7 + w] = part * SCALE;
    }
}

// ---------------------------------------------------------------------------
// Kernel 2: the big pass. For each token: LN on the fly, 7 dots vs ug,
// softmax over 7 (+EPS), accumulate P += a * x_hat and denom += a.
// grid = 64 batches x 4 chunks; each CTA: 4 passes of 256 tokens.
// ---------------------------------------------------------------------------
__global__ void __launch_bounds__(256, 2)
attn_pass(const float* __restrict__ inp)
{
    extern __shared__ float sm[];
    float* Xs = sm;                  // [256][68] tokens (raw then normalized)
    float* Ug = Xs + 256*68;         // [7][64]
    float* Ub = Ug + 448;            // [7] (+1 pad)
    float* As = Ub + 8;              // [7][257] attn weights

    int tid = threadIdx.x;
    int blk = blockIdx.x;
    int b = blk >> 2;
    int chunk = blk & 3;

    for (int idx = tid; idx < 448; idx += 256) Ug[idx] = g_ug[b*448 + idx];
    if (tid < 7) Ub[tid] = g_ub[b*7 + tid];

    // P-phase accumulators (threads 0..223): (half over t, i=0..6, c4=0..15)
    float p0=0.f, p1=0.f, p2=0.f, p3=0.f, dsum=0.f;
    int half = tid / 112;
    int rr   = tid - half*112;
    int pi   = rr >> 4;
    int pc4  = rr & 15;

    const float4* in4 = reinterpret_cast<const float4*>(inp)
                      + (size_t)(b*4096 + chunk*1024) * 16;

    for (int pass = 0; pass < 4; pass++) {
        __syncthreads();                       // protect Xs/As vs previous P-phase
        // ---- load 256 tokens, coalesced ----
        const float4* src = in4 + pass*256*16;
        #pragma unroll
        for (int k = 0; k < 16; k++) {
            int idx = tid + k*256;
            int t = idx >> 4, c4 = idx & 15;
            float4 v = src[idx];
            *reinterpret_cast<float4*>(&Xs[t*68 + c4*4]) = v;
        }
        __syncthreads();
        // ---- per-token: LN + dots + softmax ----
        {
            int t = tid;
            float4 xr[16];
            float s = 0.f, ss = 0.f;
            #pragma unroll
            for (int q = 0; q < 16; q++) {
                xr[q] = *reinterpret_cast<float4*>(&Xs[t*68 + q*4]);
                s  += xr[q].x + xr[q].y + xr[q].z + xr[q].w;
                ss += xr[q].x*xr[q].x + xr[q].y*xr[q].y + xr[q].z*xr[q].z + xr[q].w*xr[q].w;
            }
            float m   = s * (1.0f/64.0f);
            float inv = rsqrtf(ss * (1.0f/64.0f) - m*m + LN_EPS);
            float d[7];
            #pragma unroll
            for (int i = 0; i < 7; i++) d[i] = Ub[i];
            #pragma unroll
            for (int q = 0; q < 16; q++) {
                float4 xh;
                xh.x = (xr[q].x - m)*inv;
                xh.y = (xr[q].y - m)*inv;
                xh.z = (xr[q].z - m)*inv;
                xh.w = (xr[q].w - m)*inv;
                #pragma unroll
                for (int i = 0; i < 7; i++) {
                    float4 u = *reinterpret_cast<const float4*>(&Ug[i*64 + q*4]);
                    d[i] += u.x*xh.x + u.y*xh.y + u.z*xh.z + u.w*xh.w;
                }
                *reinterpret_cast<float4*>(&Xs[t*68 + q*4]) = xh;  // store normalized
            }
            float mx = d[0];
            #pragma unroll
            for (int i = 1; i < 7; i++) mx = fmaxf(mx, d[i]);
            float e[7], se = 0.f;
            #pragma unroll
            for (int i = 0; i < 7; i++) { e[i] = __expf(d[i] - mx); se += e[i]; }
            float rinv = 1.0f / se;
            #pragma unroll
            for (int i = 0; i < 7; i++) As[i*257 + t] = e[i]*rinv + EPSA;
        }
        __syncthreads();
        // ---- P accumulation: P[i][c] += a[i][t] * xhat[t][c] ----
        if (tid < 224) {
            int tb = half * 128;
            #pragma unroll 4
            for (int t = 0; t < 128; t++) {
                float a  = As[pi*257 + tb + t];
                float4 x = *reinterpret_cast<float4*>(&Xs[(tb + t)*68 + pc4*4]);
                p0 += a*x.x; p1 += a*x.y; p2 += a*x.z; p3 += a*x.w;
                dsum += a;
            }
        }
    }
    __syncthreads();
    // merge halves, write partials
    if (tid < 224 && half == 1) {
        float* buf = &Xs[rr*8];
        buf[0]=p0; buf[1]=p1; buf[2]=p2; buf[3]=p3; buf[4]=dsum;
    }
    __syncthreads();
    if (tid < 112) {
        float* buf = &Xs[tid*8];
        p0 += buf[0]; p1 += buf[1]; p2 += buf[2]; p3 += buf[3]; dsum += buf[4];
        int o = blk*448 + pi*64 + pc4*4;
        g_P[o+0]=p0; g_P[o+1]=p1; g_P[o+2]=p2; g_P[o+3]=p3;
        if (pc4 == 0) g_D[blk*7 + pi] = dsum;
    }
}

// ---------------------------------------------------------------------------
// Kernel 3: per-batch reduce + Wv projection + GRU + FFN. Deterministic.
// ---------------------------------------------------------------------------
__global__ void slot_update(const float* __restrict__ Wv, const float* __restrict__ bv,
                            const float* __restrict__ W_ih, const float* __restrict__ W_hh,
                            const float* __restrict__ b_ih, const float* __restrict__ b_hh,
                            const float* __restrict__ W1, const float* __restrict__ b1,
                            const float* __restrict__ W2, const float* __restrict__ b2,
                            const float* __restrict__ g_in, const float* __restrict__ be_in,
                            const float* __restrict__ g_ff, const float* __restrict__ be_ff,
                            float* __restrict__ outp)
{
    __shared__ float sP[448];
    __shared__ float sden[7];
    __shared__ float sxa[448];
    __shared__ float supd[448];
    __shared__ float sh_h[448];
    __shared__ float sgi[1344];
    __shared__ float sgh[1344];
    __shared__ float snew[448];
    __shared__ float sff[448];
    __shared__ float sy1[896];
    int b = blockIdx.x, tid = threadIdx.x;

    for (int idx = tid; idx < 448; idx += 256) {
        float s = 0.f;
        #pragma unroll
        for (int ch = 0; ch < 4; ch++) s += g_P[(b*4 + ch)*448 + idx];
        sP[idx] = s;
        sh_h[idx] = g_slots[b*448 + idx];
    }
    if (tid < 7) {
        float s = 0.f;
        #pragma unroll
        for (int ch = 0; ch < 4; ch++) s += g_D[(b*4 + ch)*7 + tid];
        sden[tid] = s;
    }
    __syncthreads();
    // attention-weighted mean back to x-space (g_in, be_in; sum(attn)=1)
    for (int idx = tid; idx < 448; idx += 256) {
        int e = idx & 63, i = idx >> 6;
        sxa[idx] = sP[idx] / sden[i] * g_in[e] + be_in[e];
    }
    __syncthreads();
    // updates = xa @ Wv^T + bv
    for (int idx = tid; idx < 448; idx += 256) {
        int c = idx & 63, i = idx >> 6;
        float acc = bv[c];
        for (int e = 0; e < 64; e++) acc += sxa[i*64 + e] * Wv[c*64 + e];
        supd[idx] = acc;
    }
    __syncthreads();
    // GRU gate pre-activations
    for (int idx = tid; idx < 1344; idx += 256) {
        int i = idx / 192, r = idx - i*192;
        float ai = b_ih[r], ah = b_hh[r];
        for (int c = 0; c < 64; c++) {
            ai += supd[i*64 + c] * W_ih[r*64 + c];
            ah += sh_h[i*64 + c] * W_hh[r*64 + c];
        }
        sgi[idx] = ai; sgh[idx] = ah;
    }
    __syncthreads();
    for (int idx = tid; idx < 448; idx += 256) {
        int c = idx & 63, i = idx >> 6;
        float rg = 1.0f / (1.0f + __expf(-(sgi[i*192 + c]       + sgh[i*192 + c])));
        float zg = 1.0f / (1.0f + __expf(-(sgi[i*192 + 64 + c]  + sgh[i*192 + 64 + c])));
        float ng = tanhf(sgi[i*192 + 128 + c] + rg * sgh[i*192 + 128 + c]);
        snew[idx] = (1.0f - zg)*ng + zg*sh_h[idx];
    }
    __syncthreads();
    // FFN layernorm
    int w = tid >> 5, lane = tid & 31;
    if (w < 7) {
        float v0 = snew[w*64 + lane], v1 = snew[w*64 + 32 + lane];
        float s = v0 + v1, ss = v0*v0 + v1*v1;
        #pragma unroll
        for (int o = 16; o; o >>= 1) {
            s  += __shfl_xor_sync(0xffffffffu, s,  o);
            ss += __shfl_xor_sync(0xffffffffu, ss, o);
        }
        float m   = s * (1.0f/64.0f);
        float inv = rsqrtf(ss * (1.0f/64.0f) - m*m + LN_EPS);
        sff[w*64 + lane]      = (v0 - m)*inv*g_ff[lane]      + be_ff[lane];
        sff[w*64 + lane + 32] = (v1 - m)*inv*g_ff[lane + 32] + be_ff[lane + 32];
    }
    __syncthreads();
    for (int idx = tid; idx < 896; idx += 256) {
        int i = idx >> 7, r = idx & 127;
        float acc = b1[r];
        for (int c = 0; c < 64; c++) acc += sff[i*64 + c] * W1[r*64 + c];
        sy1[idx] = fmaxf(acc, 0.0f);
    }
    __syncthreads();
    for (int idx = tid; idx < 448; idx += 256) {
        int c = idx & 63, i = idx >> 6;
        float acc = b2[c];
        for (int r = 0; r < 128; r++) acc += sy1[i*128 + r] * W2[c*128 + r];
        float v = snew[idx] + acc;
        g_slots[b*448 + idx] = v;
        if (outp) outp[b*448 + idx] = v;
    }
}

// ---------------------------------------------------------------------------
extern "C" void kernel_launch(void* const* d_in, const int* in_sizes, int n_in,
                              void* d_out, int out_size)
{
    const float* inputs = (const float*)d_in[0];
    // d_in[1] = positional_embeddings (unused by reference)
    const float* noise  = (const float*)d_in[2];
    const float* mu     = (const float*)d_in[3];
    const float* sigma  = (const float*)d_in[4];
    const float* Wq     = (const float*)d_in[5];
    const float* bq     = (const float*)d_in[6];
    const float* Wk     = (const float*)d_in[7];
    const float* bk     = (const float*)d_in[8];
    const float* Wv     = (const float*)d_in[9];
    const float* bv     = (const float*)d_in[10];
    const float* W_ih   = (const float*)d_in[11];
    const float* W_hh   = (const float*)d_in[12];
    const float* b_ih   = (const float*)d_in[13];
    const float* b_hh   = (const float*)d_in[14];
    const float* W1     = (const float*)d_in[15];
    const float* b1     = (const float*)d_in[16];
    const float* W2     = (const float*)d_in[17];
    const float* b2     = (const float*)d_in[18];
    const float* gin    = (const float*)d_in[19];
    const float* bein   = (const float*)d_in[20];
    const float* gsl    = (const float*)d_in[21];
    const float* besl   = (const float*)d_in[22];
    const float* gff    = (const float*)d_in[23];
    const float* beff   = (const float*)d_in[24];

    const int SMEM = (256*68 + 448 + 8 + 7*257) * 4;
    cudaFuncSetAttribute(attn_pass, cudaFuncAttributeMaxDynamicSharedMemorySize, SMEM);

    for (int it = 0; it < 3; it++) {
        slot_prep<<<64, 256>>>(noise, mu, sigma, Wq, bq, Wk, bk,
                               gsl, besl, gin, bein, it == 0 ? 1 : 0);
        attn_pass<<<256, 256, SMEM>>>(inputs);
        slot_update<<<64, 256>>>(Wv, bv, W_ih, W_hh, b_ih, b_hh,
                                 W1, b1, W2, b2, gin, bein, gff, beff,
                                 it == 2 ? (float*)d_out : nullptr);
    }
}